// round 15
// baseline (speedup 1.0000x reference)
#include <cuda_runtime.h>
#include <cuda_fp16.h>
#include <math.h>

#define NN 50000
#define D 128
#define EMAX 800000
#define TILE 1024
#define NPART ((NN + TILE - 1) / TILE)   // 49
#define GEMM_BLOCKS ((NN + 63) / 64)     // 782
#define WPAD 136
#define SPLITW_BLOCKS (4 * D * D / 256)  // 256

// ---- device scratch (no allocations allowed; zero-initialized at load) ----
__device__ __half g_ga[(size_t)NN * D];   // fp16 message buffers (pre-activation)
__device__ __half g_gb[(size_t)NN * D];
__device__ __half g_acth[(size_t)NN * D]; // fp16 activation buffer (layers 1,3)
__device__ float g_dinv1[NN];
__device__ float g_dinv2[NN];
__device__ int   g_cnt1[NN];              // kept zeroed by scan_tiles_kernel
__device__ int   g_cnt2[NN];
__device__ int   g_rowptr1[NN + 1];
__device__ int   g_rowptr2[NN + 1];
__device__ int   g_cursor1[NN];
__device__ int   g_cursor2[NN];
__device__ int   g_col1[EMAX];
__device__ int   g_col2[EMAX];
__device__ int   g_part1[NPART];
__device__ int   g_part2[NPART];
__device__ float g_whi[4 * D * D];        // tf32-rounded hi parts of W1..W4
__device__ float g_wlo[4 * D * D];        // tf32-rounded lo parts

// ---- tf32 helpers ----
__device__ __forceinline__ unsigned f2tf32(float f) {
    unsigned r;
    asm("cvt.rna.tf32.f32 %0, %1;" : "=r"(r) : "f"(f));
    return r;
}
__device__ __forceinline__ void mma_tf32(float* c, const unsigned* a,
                                         unsigned b0, unsigned b1) {
    asm volatile(
        "mma.sync.aligned.m16n8k8.row.col.f32.tf32.tf32.f32 "
        "{%0,%1,%2,%3}, {%4,%5,%6,%7}, {%8,%9}, {%0,%1,%2,%3};"
        : "+f"(c[0]), "+f"(c[1]), "+f"(c[2]), "+f"(c[3])
        : "r"(a[0]), "r"(a[1]), "r"(a[2]), "r"(a[3]), "r"(b0), "r"(b1));
}

// ---------------------------------------------------------------------------
// Merged: W tf32-split (blocks [0, SPLITW_BLOCKS)) + degree count (rest).
// Count does 8 edges/thread (4x int2): more independent ATOMG chains in
// flight and a single thread-wave.
__global__ void splitw_count_kernel(
    const float* __restrict__ W1, const float* __restrict__ W2,
    const float* __restrict__ W3, const float* __restrict__ W4,
    float* __restrict__ whi, float* __restrict__ wlo,
    const int* __restrict__ ei1, int E1,
    const int* __restrict__ ei2, int E2,
    int* __restrict__ c1, int* __restrict__ c2,
    int* __restrict__ rp1, int* __restrict__ rp2)
{
    if (blockIdx.x < SPLITW_BLOCKS) {
        int i = blockIdx.x * blockDim.x + threadIdx.x;
        int l = i >> 14;
        int j = i & 16383;
        const float* W = (l == 0) ? W1 : (l == 1) ? W2 : (l == 2) ? W3 : W4;
        float f = W[j];
        float hf = __uint_as_float(f2tf32(f));
        whi[i] = hf;
        wlo[i] = __uint_as_float(f2tf32(f - hf));
        if (i == 0) { rp1[NN] = E1; rp2[NN] = E2; }
        return;
    }
    int o1 = E1 >> 3, o2 = E2 >> 3;
    int i = (blockIdx.x - SPLITW_BLOCKS) * blockDim.x + threadIdx.x;
    if (i < o1) {
        const int2* dp = reinterpret_cast<const int2*>(ei1 + E1);
        #pragma unroll
        for (int q = 0; q < 4; q++) {
            int2 d = dp[4 * i + q];
            atomicAdd(&c1[d.x], 1);
            atomicAdd(&c1[d.y], 1);
        }
    } else if (i < o1 + o2) {
        const int2* dp = reinterpret_cast<const int2*>(ei2 + E2);
        int ii = i - o1;
        #pragma unroll
        for (int q = 0; q < 4; q++) {
            int2 d = dp[4 * ii + q];
            atomicAdd(&c2[d.x], 1);
            atomicAdd(&c2[d.y], 1);
        }
    } else {
        int k = i - o1 - o2;
        if (k < 8) {
            int e = 8 * o1 + k;
            if (e < E1) atomicAdd(&c1[ei1[E1 + e]], 1);
        } else if (k < 16) {
            int e = 8 * o2 + (k - 8);
            if (e < E2) atomicAdd(&c2[ei2[E2 + e]], 1);
        }
    }
}

__global__ __launch_bounds__(256) void partial_dinv_kernel(
    const int* __restrict__ c1, float* __restrict__ d1, int* __restrict__ p1,
    const int* __restrict__ c2, float* __restrict__ d2, int* __restrict__ p2)
{
    int set = (blockIdx.x >= NPART) ? 1 : 0;
    int b = blockIdx.x - set * NPART;
    const int* c = set ? c2 : c1;
    float* dv    = set ? d2 : d1;
    int* part    = set ? p2 : p1;

    __shared__ int wsum[8];
    int tid = threadIdx.x;
    int base = b * TILE + tid * 4;
    int s = 0;
    #pragma unroll
    for (int k = 0; k < 4; k++) {
        int i = base + k;
        if (i < NN) {
            int v = c[i];
            s += v;
            dv[i] = rsqrtf((float)v + 1.0f);
        }
    }
    #pragma unroll
    for (int off = 16; off > 0; off >>= 1)
        s += __shfl_down_sync(0xFFFFFFFFu, s, off);
    if ((tid & 31) == 0) wsum[tid >> 5] = s;
    __syncthreads();
    if (tid < 8) {
        int t = wsum[tid];
        #pragma unroll
        for (int off = 4; off > 0; off >>= 1)
            t += __shfl_down_sync(0xFFu, t, off);
        if (tid == 0) part[b] = t;
    }
}

// Per-tile scan; block offset computed in-block from raw tile sums (part[]).
// Also zeroes cnt (maintains counts-are-zero invariant for graph replay).
__global__ __launch_bounds__(1024) void scan_tiles_kernel(
    int* __restrict__ c1, int* __restrict__ rp1, int* __restrict__ cur1,
    const int* __restrict__ p1,
    int* __restrict__ c2, int* __restrict__ rp2, int* __restrict__ cur2,
    const int* __restrict__ p2)
{
    int set = (blockIdx.x >= NPART) ? 1 : 0;
    int b = blockIdx.x - set * NPART;
    int* cnt        = set ? c2 : c1;
    int* rp         = set ? rp2 : rp1;
    int* cur        = set ? cur2 : cur1;
    const int* part = set ? p2 : p1;

    __shared__ int warp_sums[32];
    __shared__ int s_off;
    int tid = threadIdx.x;
    int lane = tid & 31;
    int wid = tid >> 5;

    if (tid == 0) s_off = 0;
    __syncthreads();
    if (tid < b) atomicAdd(&s_off, part[tid]);   // b <= 48 raw tile sums

    int i = b * TILE + tid;
    int v = (i < NN) ? cnt[i] : 0;
    int incl = v;
    #pragma unroll
    for (int off = 1; off < 32; off <<= 1) {
        int t = __shfl_up_sync(0xFFFFFFFFu, incl, off);
        if (lane >= off) incl += t;
    }
    if (lane == 31) warp_sums[wid] = incl;
    __syncthreads();
    if (wid == 0) {
        int s = warp_sums[lane];
        #pragma unroll
        for (int off = 1; off < 32; off <<= 1) {
            int t = __shfl_up_sync(0xFFFFFFFFu, s, off);
            if (lane >= off) s += t;
        }
        warp_sums[lane] = s;
    }
    __syncthreads();
    int woff = (wid > 0) ? warp_sums[wid - 1] : 0;
    int excl = incl - v + woff + s_off;
    if (i < NN) { rp[i] = excl; cur[i] = excl; cnt[i] = 0; }
}

// CSR fill: 8 edges/thread (4x int2) — single thread-wave, 8 independent
// ATOMG chains per thread for latency hiding.
__global__ void fill_both_kernel(const int* __restrict__ ei1, int E1,
                                 int* __restrict__ cur1, int* __restrict__ col1,
                                 const int* __restrict__ ei2, int E2,
                                 int* __restrict__ cur2, int* __restrict__ col2)
{
    int o1 = E1 >> 3, o2 = E2 >> 3;
    int i = blockIdx.x * blockDim.x + threadIdx.x;
    if (i < o1) {
        const int2* sp = reinterpret_cast<const int2*>(ei1);
        const int2* dp = reinterpret_cast<const int2*>(ei1 + E1);
        int2 s[4], d[4];
        #pragma unroll
        for (int q = 0; q < 4; q++) { s[q] = sp[4 * i + q]; d[q] = dp[4 * i + q]; }
        int p[8];
        #pragma unroll
        for (int q = 0; q < 4; q++) {
            p[2 * q]     = atomicAdd(&cur1[d[q].x], 1);
            p[2 * q + 1] = atomicAdd(&cur1[d[q].y], 1);
        }
        #pragma unroll
        for (int q = 0; q < 4; q++) {
            col1[p[2 * q]]     = s[q].x;
            col1[p[2 * q + 1]] = s[q].y;
        }
    } else if (i < o1 + o2) {
        int ii = i - o1;
        const int2* sp = reinterpret_cast<const int2*>(ei2);
        const int2* dp = reinterpret_cast<const int2*>(ei2 + E2);
        int2 s[4], d[4];
        #pragma unroll
        for (int q = 0; q < 4; q++) { s[q] = sp[4 * ii + q]; d[q] = dp[4 * ii + q]; }
        int p[8];
        #pragma unroll
        for (int q = 0; q < 4; q++) {
            p[2 * q]     = atomicAdd(&cur2[d[q].x], 1);
            p[2 * q + 1] = atomicAdd(&cur2[d[q].y], 1);
        }
        #pragma unroll
        for (int q = 0; q < 4; q++) {
            col2[p[2 * q]]     = s[q].x;
            col2[p[2 * q + 1]] = s[q].y;
        }
    } else {
        int k = i - o1 - o2;
        if (k < 8) {
            int e = 8 * o1 + k;
            if (e < E1) col1[atomicAdd(&cur1[ei1[E1 + e]], 1)] = ei1[e];
        } else if (k < 16) {
            int e = 8 * o2 + (k - 8);
            if (e < E2) col2[atomicAdd(&cur2[ei2[E2 + e]], 1)] = ei2[e];
        }
    }
}

// ---------------------------------------------------------------------------
// tf32 GEMM tile: 64x128 output, 256 threads (8 warps as 4x2).
// F16A=false: fp32 A, 3-pass (ah·bh + ah·bl + al·bh).
// F16A=true:  fp16 A (exact in tf32), 2-pass (a·bh + a·bl).
// g_out (fp16) = (A[row] @ W) * dinv[row].
template <bool F16A>
__device__ __forceinline__ void gemm_tf32_tile(
    float (*As)[132], float (*Whs)[WPAD], float (*Wls)[WPAD],
    const void* __restrict__ Aptr,
    const float* __restrict__ whi, const float* __restrict__ wlo,
    const float* __restrict__ dinv, __half* __restrict__ g_out,
    int row_base, int tid)
{
    if (F16A) {
        const uint4* Ah = reinterpret_cast<const uint4*>(Aptr);
        #pragma unroll
        for (int i = tid; i < 64 * 16; i += 256) {
            int r = i >> 4, u = i & 15;
            uint4 raw = make_uint4(0u, 0u, 0u, 0u);
            if (row_base + r < NN)
                raw = Ah[(long)(row_base + r) * 16 + u];
            const __half2* hp = reinterpret_cast<const __half2*>(&raw);
            float* dst = &As[r][u * 8];
            #pragma unroll
            for (int p = 0; p < 4; p++) {
                float2 f = __half22float2(hp[p]);
                dst[p * 2]     = f.x;
                dst[p * 2 + 1] = f.y;
            }
        }
    } else {
        const float4* Af = reinterpret_cast<const float4*>(Aptr);
        #pragma unroll
        for (int i = tid; i < 64 * 32; i += 256) {
            int r = i >> 5, c4 = i & 31;
            float4 v = make_float4(0.f, 0.f, 0.f, 0.f);
            if (row_base + r < NN)
                v = Af[(long)(row_base + r) * 32 + c4];
            *reinterpret_cast<float4*>(&As[r][c4 * 4]) = v;
        }
    }

    const int lane = tid & 31;
    const int wid = tid >> 5;
    const int wm = (wid & 3) * 16;
    const int wn = (wid >> 2) * 64;
    const int g = lane >> 2;
    const int t = lane & 3;

    float acc[8][4];
    #pragma unroll
    for (int nt = 0; nt < 8; nt++)
        #pragma unroll
        for (int c = 0; c < 4; c++) acc[nt][c] = 0.0f;

    for (int kc = 0; kc < D; kc += 8) {
        __syncthreads();
        #pragma unroll
        for (int i = tid; i < 512; i += 256) {
            int m = i >> 8;
            int j = i & 255;
            int r = j >> 5, c4 = j & 31;
            const float4* src = reinterpret_cast<const float4*>(m ? wlo : whi);
            float4 v = src[(kc + r) * 32 + c4];
            float (*dst)[WPAD] = m ? Wls : Whs;
            *reinterpret_cast<float4*>(&dst[r][c4 * 4]) = v;
        }
        __syncthreads();

        float af[4] = { As[wm + g][kc + t],     As[wm + g + 8][kc + t],
                        As[wm + g][kc + t + 4], As[wm + g + 8][kc + t + 4] };
        unsigned ah[4], al[4];
        #pragma unroll
        for (int q = 0; q < 4; q++) {
            ah[q] = f2tf32(af[q]);
            if (!F16A)
                al[q] = f2tf32(af[q] - __uint_as_float(ah[q]));
        }

        #pragma unroll
        for (int nt = 0; nt < 8; nt++) {
            int c = wn + nt * 8 + g;
            unsigned bh0 = __float_as_uint(Whs[t][c]);
            unsigned bh1 = __float_as_uint(Whs[t + 4][c]);
            unsigned bl0 = __float_as_uint(Wls[t][c]);
            unsigned bl1 = __float_as_uint(Wls[t + 4][c]);
            mma_tf32(acc[nt], ah, bh0, bh1);
            mma_tf32(acc[nt], ah, bl0, bl1);
            if (!F16A) mma_tf32(acc[nt], al, bh0, bh1);
        }
    }

    int r0 = row_base + wm + g;
    int r1 = r0 + 8;
    float d0 = (r0 < NN) ? dinv[r0] : 0.0f;
    float d1 = (r1 < NN) ? dinv[r1] : 0.0f;
    #pragma unroll
    for (int nt = 0; nt < 8; nt++) {
        int c = wn + nt * 8 + t * 2;
        if (r0 < NN) {
            __half2 h = __float22half2_rn(
                make_float2(acc[nt][0] * d0, acc[nt][1] * d0));
            *reinterpret_cast<__half2*>(&g_out[(long)r0 * D + c]) = h;
        }
        if (r1 < NN) {
            __half2 h = __float22half2_rn(
                make_float2(acc[nt][2] * d1, acc[nt][3] * d1));
            *reinterpret_cast<__half2*>(&g_out[(long)r1 * D + c]) = h;
        }
    }
}

__global__ __launch_bounds__(256) void gemm_tf32_f32_kernel(
    const float* __restrict__ A,
    const float* __restrict__ whi, const float* __restrict__ wlo,
    const float* __restrict__ dinv, __half* __restrict__ g_out)
{
    __shared__ float As[64][132];
    __shared__ float Whs[8][WPAD];
    __shared__ float Wls[8][WPAD];
    gemm_tf32_tile<false>(As, Whs, Wls, A, whi, wlo, dinv, g_out,
                          blockIdx.x * 64, threadIdx.x);
}

__global__ __launch_bounds__(256) void gemm_tf32_f16_kernel(
    const __half* __restrict__ A,
    const float* __restrict__ whi, const float* __restrict__ wlo,
    const float* __restrict__ dinv, __half* __restrict__ g_out)
{
    __shared__ float As[64][132];
    __shared__ float Whs[8][WPAD];
    __shared__ float Wls[8][WPAD];
    gemm_tf32_tile<true>(As, Whs, Wls, A, whi, wlo, dinv, g_out,
                         blockIdx.x * 64, threadIdx.x);
}

// ---------------------------------------------------------------------------
// Gather + finalize over fp16 messages: one warp per node, 4-way unrolled,
// with col-index prefetch (next batch's indices load while current rows
// are in flight — breaks the col->row serial latency chain).
__device__ __forceinline__ void acc_half4(float4& a, uint2 raw) {
    __half2 h0 = *reinterpret_cast<__half2*>(&raw.x);
    __half2 h1 = *reinterpret_cast<__half2*>(&raw.y);
    float2 f0 = __half22float2(h0);
    float2 f1 = __half22float2(h1);
    a.x += f0.x; a.y += f0.y; a.z += f1.x; a.w += f1.y;
}

__global__ __launch_bounds__(256) void gather_finalize_kernel(
    const uint2* __restrict__ g, const int* __restrict__ row_ptr,
    const int* __restrict__ col, const float* __restrict__ dinv,
    const float4* __restrict__ b,
    uint2* __restrict__ out_h, float4* __restrict__ out_f, int relu_mode)
{
    int warp = (blockIdx.x * blockDim.x + threadIdx.x) >> 5;
    int lane = threadIdx.x & 31;
    if (warp >= NN) return;

    long base = (long)warp * 32 + lane;
    float4 a0 = make_float4(0.f, 0.f, 0.f, 0.f);
    float4 a1 = make_float4(0.f, 0.f, 0.f, 0.f);
    float4 a2 = make_float4(0.f, 0.f, 0.f, 0.f);
    float4 a3 = make_float4(0.f, 0.f, 0.f, 0.f);
    acc_half4(a0, g[base]);                     // self-loop term

    int jb = __ldg(&row_ptr[warp]);
    int je = __ldg(&row_ptr[warp + 1]);
    int j = jb;

    int c0 = 0, c1 = 0, c2 = 0, c3 = 0;
    if (j + 3 < je) {
        c0 = __ldg(&col[j]);     c1 = __ldg(&col[j + 1]);
        c2 = __ldg(&col[j + 2]); c3 = __ldg(&col[j + 3]);
    }
    while (j + 3 < je) {
        int jn = j + 4;
        int n0 = 0, n1 = 0, n2 = 0, n3 = 0;
        if (jn + 3 < je) {                       // prefetch next batch
            n0 = __ldg(&col[jn]);     n1 = __ldg(&col[jn + 1]);
            n2 = __ldg(&col[jn + 2]); n3 = __ldg(&col[jn + 3]);
        }
        uint2 v0 = g[(long)c0 * 32 + lane];
        uint2 v1 = g[(long)c1 * 32 + lane];
        uint2 v2 = g[(long)c2 * 32 + lane];
        uint2 v3 = g[(long)c3 * 32 + lane];
        acc_half4(a0, v0); acc_half4(a1, v1);
        acc_half4(a2, v2); acc_half4(a3, v3);
        c0 = n0; c1 = n1; c2 = n2; c3 = n3;
        j = jn;
    }
    for (; j < je; j++) {
        int s = __ldg(&col[j]);
        acc_half4(a0, g[(long)s * 32 + lane]);
    }
    a0.x += a1.x + a2.x + a3.x;
    a0.y += a1.y + a2.y + a3.y;
    a0.z += a1.z + a2.z + a3.z;
    a0.w += a1.w + a2.w + a3.w;

    float dv = dinv[warp];
    float4 bb = b[lane];
    float o[4] = { fmaf(a0.x, dv, bb.x), fmaf(a0.y, dv, bb.y),
                   fmaf(a0.z, dv, bb.z), fmaf(a0.w, dv, bb.w) };
    if (relu_mode) {
        #pragma unroll
        for (int k = 0; k < 4; k++) o[k] = fmaxf(o[k], 0.0f);
    } else {
        #pragma unroll
        for (int k = 0; k < 4; k++) o[k] = (o[k] > 0.0f) ? o[k] : expm1f(o[k]);
    }
    if (out_h) {
        __half2 h0 = __floats2half2_rn(o[0], o[1]);
        __half2 h1 = __floats2half2_rn(o[2], o[3]);
        uint2 packed;
        packed.x = *reinterpret_cast<unsigned*>(&h0);
        packed.y = *reinterpret_cast<unsigned*>(&h1);
        out_h[base] = packed;
    } else {
        out_f[base] = make_float4(o[0], o[1], o[2], o[3]);
    }
}

// ---------------------------------------------------------------------------
extern "C" void kernel_launch(void* const* d_in, const int* in_sizes, int n_in,
                              void* d_out, int out_size)
{
    const float* x  = (const float*)d_in[0];
    const float* W1 = (const float*)d_in[1]; const float* b1 = (const float*)d_in[2];
    const float* W2 = (const float*)d_in[3]; const float* b2 = (const float*)d_in[4];
    const float* W3 = (const float*)d_in[5]; const float* b3 = (const float*)d_in[6];
    const float* W4 = (const float*)d_in[7]; const float* b4 = (const float*)d_in[8];
    const int* ei1 = (const int*)d_in[9];
    const int* ei2 = (const int*)d_in[10];
    const int E1 = in_sizes[9] / 2;
    const int E2 = in_sizes[10] / 2;

    __half *ga, *gb, *acth;
    float *dinv1, *dinv2, *whi, *wlo;
    int *cnt1, *cnt2, *rp1, *rp2, *cur1, *cur2, *col1, *col2, *p1, *p2;
    cudaGetSymbolAddress((void**)&ga,   g_ga);
    cudaGetSymbolAddress((void**)&gb,   g_gb);
    cudaGetSymbolAddress((void**)&acth, g_acth);
    cudaGetSymbolAddress((void**)&dinv1, g_dinv1);
    cudaGetSymbolAddress((void**)&dinv2, g_dinv2);
    cudaGetSymbolAddress((void**)&cnt1, g_cnt1);
    cudaGetSymbolAddress((void**)&cnt2, g_cnt2);
    cudaGetSymbolAddress((void**)&rp1,  g_rowptr1);
    cudaGetSymbolAddress((void**)&rp2,  g_rowptr2);
    cudaGetSymbolAddress((void**)&cur1, g_cursor1);
    cudaGetSymbolAddress((void**)&cur2, g_cursor2);
    cudaGetSymbolAddress((void**)&col1, g_col1);
    cudaGetSymbolAddress((void**)&col2, g_col2);
    cudaGetSymbolAddress((void**)&p1,   g_part1);
    cudaGetSymbolAddress((void**)&p2,   g_part2);
    cudaGetSymbolAddress((void**)&whi,  g_whi);
    cudaGetSymbolAddress((void**)&wlo,  g_wlo);

    float* out_z = (float*)d_out;
    float* out_x = (float*)d_out + (long)NN * D;

    const int gat_blocks  = (NN * 32 + 255) / 256;
    const int nedge8 = (E1 >> 3) + (E2 >> 3) + 16;
    const int edge_blocks = (nedge8 + 255) / 256;

    // ---- CSR build ----
    splitw_count_kernel<<<SPLITW_BLOCKS + edge_blocks, 256>>>(
        W1, W2, W3, W4, whi, wlo, ei1, E1, ei2, E2, cnt1, cnt2, rp1, rp2);
    partial_dinv_kernel<<<2 * NPART, 256>>>(cnt1, dinv1, p1, cnt2, dinv2, p2);
    scan_tiles_kernel<<<2 * NPART, 1024>>>(cnt1, rp1, cur1, p1, cnt2, rp2, cur2, p2);
    fill_both_kernel<<<edge_blocks, 256>>>(ei1, E1, cur1, col1, ei2, E2, cur2, col2);

    // gemm1 (fp32 A, 3-pass): ga = (x @ W1) * dinv1
    gemm_tf32_f32_kernel<<<GEMM_BLOCKS, 256>>>(x, whi + 0 * D * D, wlo + 0 * D * D,
                                               dinv1, ga);
    // gather1 (elu) -> acth (fp16)
    gather_finalize_kernel<<<gat_blocks, 256>>>(
        (const uint2*)ga, rp1, col1, dinv1, (const float4*)b1,
        (uint2*)acth, nullptr, 0);
    // gemm2 (fp16 A, 2-pass): acth -> gb (*dinv2)
    gemm_tf32_f16_kernel<<<GEMM_BLOCKS, 256>>>(acth, whi + 1 * D * D, wlo + 1 * D * D,
                                               dinv2, gb);
    // gather2 (elu) -> out_z (fp32; layer-3 GEMM reads it directly)
    gather_finalize_kernel<<<gat_blocks, 256>>>(
        (const uint2*)gb, rp2, col2, dinv2, (const float4*)b2,
        nullptr, (float4*)out_z, 0);
    // gemm3 (fp32 A, 3-pass): out_z -> ga (*dinv1)
    gemm_tf32_f32_kernel<<<GEMM_BLOCKS, 256>>>(out_z, whi + 2 * D * D, wlo + 2 * D * D,
                                               dinv1, ga);
    // gather3 (elu) -> acth (fp16)
    gather_finalize_kernel<<<gat_blocks, 256>>>(
        (const uint2*)ga, rp1, col1, dinv1, (const float4*)b3,
        (uint2*)acth, nullptr, 0);
    // gemm4 (fp16 A, 2-pass): acth -> gb (*dinv2)
    gemm_tf32_f16_kernel<<<GEMM_BLOCKS, 256>>>(acth, whi + 3 * D * D, wlo + 3 * D * D,
                                               dinv2, gb);
    // gather4 (relu) -> out_x (fp32)
    gather_finalize_kernel<<<gat_blocks, 256>>>(
        (const uint2*)gb, rp2, col2, dinv2, (const float4*)b4,
        nullptr, (float4*)out_x, 1);
}

// round 16
// speedup vs baseline: 1.0429x; 1.0429x over previous
#include <cuda_runtime.h>
#include <cuda_fp16.h>
#include <math.h>

#define NN 50000
#define D 128
#define EMAX 800000
#define TILE 1024
#define NPART ((NN + TILE - 1) / TILE)   // 49
#define GEMM_BLOCKS ((NN + 63) / 64)     // 782
#define WPAD 136
#define SPLITW_BLOCKS (4 * D * D / 256)  // 256

// ---- device scratch (no allocations allowed; zero-initialized at load) ----
__device__ __half g_ga[(size_t)NN * D];   // fp16 message buffers (pre-activation)
__device__ __half g_gb[(size_t)NN * D];
__device__ __half g_acth[(size_t)NN * D]; // fp16 activation buffer (layers 1,3)
__device__ float g_dinv1[NN];
__device__ float g_dinv2[NN];
__device__ int   g_cnt1[NN];              // kept zeroed by scan_tiles_kernel
__device__ int   g_cnt2[NN];
__device__ int   g_rowptr1[NN + 1];
__device__ int   g_rowptr2[NN + 1];
__device__ int   g_cursor1[NN];
__device__ int   g_cursor2[NN];
__device__ int   g_col1[EMAX];
__device__ int   g_col2[EMAX];
__device__ int   g_part1[NPART];
__device__ int   g_part2[NPART];
__device__ float g_whi[4 * D * D];        // tf32-rounded hi parts of W1..W4
__device__ float g_wlo[4 * D * D];        // tf32-rounded lo parts

// ---- tf32 helpers ----
__device__ __forceinline__ unsigned f2tf32(float f) {
    unsigned r;
    asm("cvt.rna.tf32.f32 %0, %1;" : "=r"(r) : "f"(f));
    return r;
}
__device__ __forceinline__ void mma_tf32(float* c, const unsigned* a,
                                         unsigned b0, unsigned b1) {
    asm volatile(
        "mma.sync.aligned.m16n8k8.row.col.f32.tf32.tf32.f32 "
        "{%0,%1,%2,%3}, {%4,%5,%6,%7}, {%8,%9}, {%0,%1,%2,%3};"
        : "+f"(c[0]), "+f"(c[1]), "+f"(c[2]), "+f"(c[3])
        : "r"(a[0]), "r"(a[1]), "r"(a[2]), "r"(a[3]), "r"(b0), "r"(b1));
}

// ---------------------------------------------------------------------------
// Merged: W tf32-split (blocks [0, SPLITW_BLOCKS)) + degree count (rest).
// Count at 2 edges/thread — measured-best grid size for scattered atomics.
__global__ void splitw_count_kernel(
    const float* __restrict__ W1, const float* __restrict__ W2,
    const float* __restrict__ W3, const float* __restrict__ W4,
    float* __restrict__ whi, float* __restrict__ wlo,
    const int* __restrict__ ei1, int E1,
    const int* __restrict__ ei2, int E2,
    int* __restrict__ c1, int* __restrict__ c2,
    int* __restrict__ rp1, int* __restrict__ rp2)
{
    if (blockIdx.x < SPLITW_BLOCKS) {
        int i = blockIdx.x * blockDim.x + threadIdx.x;
        int l = i >> 14;
        int j = i & 16383;
        const float* W = (l == 0) ? W1 : (l == 1) ? W2 : (l == 2) ? W3 : W4;
        float f = W[j];
        float hf = __uint_as_float(f2tf32(f));
        whi[i] = hf;
        wlo[i] = __uint_as_float(f2tf32(f - hf));
        if (i == 0) { rp1[NN] = E1; rp2[NN] = E2; }
        return;
    }
    int h1 = E1 >> 1, h2 = E2 >> 1;
    int i = (blockIdx.x - SPLITW_BLOCKS) * blockDim.x + threadIdx.x;
    if (i < h1) {
        int2 d = reinterpret_cast<const int2*>(ei1 + E1)[i];
        atomicAdd(&c1[d.x], 1);
        atomicAdd(&c1[d.y], 1);
    } else if (i < h1 + h2) {
        int2 d = reinterpret_cast<const int2*>(ei2 + E2)[i - h1];
        atomicAdd(&c2[d.x], 1);
        atomicAdd(&c2[d.y], 1);
    } else {
        int k = i - h1 - h2;
        if (k == 0 && (E1 & 1)) atomicAdd(&c1[ei1[E1 + E1 - 1]], 1);
        if (k == 1 && (E2 & 1)) atomicAdd(&c2[ei2[E2 + E2 - 1]], 1);
    }
}

__global__ __launch_bounds__(256) void partial_dinv_kernel(
    const int* __restrict__ c1, float* __restrict__ d1, int* __restrict__ p1,
    const int* __restrict__ c2, float* __restrict__ d2, int* __restrict__ p2)
{
    int set = (blockIdx.x >= NPART) ? 1 : 0;
    int b = blockIdx.x - set * NPART;
    const int* c = set ? c2 : c1;
    float* dv    = set ? d2 : d1;
    int* part    = set ? p2 : p1;

    __shared__ int wsum[8];
    int tid = threadIdx.x;
    int base = b * TILE + tid * 4;
    int s = 0;
    #pragma unroll
    for (int k = 0; k < 4; k++) {
        int i = base + k;
        if (i < NN) {
            int v = c[i];
            s += v;
            dv[i] = rsqrtf((float)v + 1.0f);
        }
    }
    #pragma unroll
    for (int off = 16; off > 0; off >>= 1)
        s += __shfl_down_sync(0xFFFFFFFFu, s, off);
    if ((tid & 31) == 0) wsum[tid >> 5] = s;
    __syncthreads();
    if (tid < 8) {
        int t = wsum[tid];
        #pragma unroll
        for (int off = 4; off > 0; off >>= 1)
            t += __shfl_down_sync(0xFFu, t, off);
        if (tid == 0) part[b] = t;
    }
}

// Per-tile scan; block offset computed in-block from raw tile sums (part[]).
// Also zeroes cnt (maintains counts-are-zero invariant for graph replay).
__global__ __launch_bounds__(1024) void scan_tiles_kernel(
    int* __restrict__ c1, int* __restrict__ rp1, int* __restrict__ cur1,
    const int* __restrict__ p1,
    int* __restrict__ c2, int* __restrict__ rp2, int* __restrict__ cur2,
    const int* __restrict__ p2)
{
    int set = (blockIdx.x >= NPART) ? 1 : 0;
    int b = blockIdx.x - set * NPART;
    int* cnt        = set ? c2 : c1;
    int* rp         = set ? rp2 : rp1;
    int* cur        = set ? cur2 : cur1;
    const int* part = set ? p2 : p1;

    __shared__ int warp_sums[32];
    __shared__ int s_off;
    int tid = threadIdx.x;
    int lane = tid & 31;
    int wid = tid >> 5;

    if (tid == 0) s_off = 0;
    __syncthreads();
    if (tid < b) atomicAdd(&s_off, part[tid]);   // b <= 48 raw tile sums

    int i = b * TILE + tid;
    int v = (i < NN) ? cnt[i] : 0;
    int incl = v;
    #pragma unroll
    for (int off = 1; off < 32; off <<= 1) {
        int t = __shfl_up_sync(0xFFFFFFFFu, incl, off);
        if (lane >= off) incl += t;
    }
    if (lane == 31) warp_sums[wid] = incl;
    __syncthreads();
    if (wid == 0) {
        int s = warp_sums[lane];
        #pragma unroll
        for (int off = 1; off < 32; off <<= 1) {
            int t = __shfl_up_sync(0xFFFFFFFFu, s, off);
            if (lane >= off) s += t;
        }
        warp_sums[lane] = s;
    }
    __syncthreads();
    int woff = (wid > 0) ? warp_sums[wid - 1] : 0;
    int excl = incl - v + woff + s_off;
    if (i < NN) { rp[i] = excl; cur[i] = excl; cnt[i] = 0; }
}

// CSR fill: 2 edges/thread — measured-best (24.5us) grid/MLP balance.
__global__ void fill_both_kernel(const int* __restrict__ ei1, int E1,
                                 int* __restrict__ cur1, int* __restrict__ col1,
                                 const int* __restrict__ ei2, int E2,
                                 int* __restrict__ cur2, int* __restrict__ col2)
{
    int h1 = E1 >> 1, h2 = E2 >> 1;
    int i = blockIdx.x * blockDim.x + threadIdx.x;
    if (i < h1) {
        int2 s = reinterpret_cast<const int2*>(ei1)[i];
        int2 d = reinterpret_cast<const int2*>(ei1 + E1)[i];
        col1[atomicAdd(&cur1[d.x], 1)] = s.x;
        col1[atomicAdd(&cur1[d.y], 1)] = s.y;
    } else if (i < h1 + h2) {
        int2 s = reinterpret_cast<const int2*>(ei2)[i - h1];
        int2 d = reinterpret_cast<const int2*>(ei2 + E2)[i - h1];
        col2[atomicAdd(&cur2[d.x], 1)] = s.x;
        col2[atomicAdd(&cur2[d.y], 1)] = s.y;
    } else {
        int k = i - h1 - h2;
        if (k == 0 && (E1 & 1))
            col1[atomicAdd(&cur1[ei1[E1 + E1 - 1]], 1)] = ei1[E1 - 1];
        if (k == 1 && (E2 & 1))
            col2[atomicAdd(&cur2[ei2[E2 + E2 - 1]], 1)] = ei2[E2 - 1];
    }
}

// ---------------------------------------------------------------------------
// tf32 GEMM tile: 64x128 output, 256 threads (8 warps as 4x2).
// F16A=false: fp32 A, 3-pass (ah·bh + ah·bl + al·bh).
// F16A=true:  fp16 A (exact in tf32), 2-pass (a·bh + a·bl).
// g_out (fp16) = (A[row] @ W) * dinv[row].
template <bool F16A>
__device__ __forceinline__ void gemm_tf32_tile(
    float (*As)[132], float (*Whs)[WPAD], float (*Wls)[WPAD],
    const void* __restrict__ Aptr,
    const float* __restrict__ whi, const float* __restrict__ wlo,
    const float* __restrict__ dinv, __half* __restrict__ g_out,
    int row_base, int tid)
{
    if (F16A) {
        const uint4* Ah = reinterpret_cast<const uint4*>(Aptr);
        #pragma unroll
        for (int i = tid; i < 64 * 16; i += 256) {
            int r = i >> 4, u = i & 15;
            uint4 raw = make_uint4(0u, 0u, 0u, 0u);
            if (row_base + r < NN)
                raw = Ah[(long)(row_base + r) * 16 + u];
            const __half2* hp = reinterpret_cast<const __half2*>(&raw);
            float* dst = &As[r][u * 8];
            #pragma unroll
            for (int p = 0; p < 4; p++) {
                float2 f = __half22float2(hp[p]);
                dst[p * 2]     = f.x;
                dst[p * 2 + 1] = f.y;
            }
        }
    } else {
        const float4* Af = reinterpret_cast<const float4*>(Aptr);
        #pragma unroll
        for (int i = tid; i < 64 * 32; i += 256) {
            int r = i >> 5, c4 = i & 31;
            float4 v = make_float4(0.f, 0.f, 0.f, 0.f);
            if (row_base + r < NN)
                v = Af[(long)(row_base + r) * 32 + c4];
            *reinterpret_cast<float4*>(&As[r][c4 * 4]) = v;
        }
    }

    const int lane = tid & 31;
    const int wid = tid >> 5;
    const int wm = (wid & 3) * 16;
    const int wn = (wid >> 2) * 64;
    const int g = lane >> 2;
    const int t = lane & 3;

    float acc[8][4];
    #pragma unroll
    for (int nt = 0; nt < 8; nt++)
        #pragma unroll
        for (int c = 0; c < 4; c++) acc[nt][c] = 0.0f;

    for (int kc = 0; kc < D; kc += 8) {
        __syncthreads();
        #pragma unroll
        for (int i = tid; i < 512; i += 256) {
            int m = i >> 8;
            int j = i & 255;
            int r = j >> 5, c4 = j & 31;
            const float4* src = reinterpret_cast<const float4*>(m ? wlo : whi);
            float4 v = src[(kc + r) * 32 + c4];
            float (*dst)[WPAD] = m ? Wls : Whs;
            *reinterpret_cast<float4*>(&dst[r][c4 * 4]) = v;
        }
        __syncthreads();

        float af[4] = { As[wm + g][kc + t],     As[wm + g + 8][kc + t],
                        As[wm + g][kc + t + 4], As[wm + g + 8][kc + t + 4] };
        unsigned ah[4], al[4];
        #pragma unroll
        for (int q = 0; q < 4; q++) {
            ah[q] = f2tf32(af[q]);
            if (!F16A)
                al[q] = f2tf32(af[q] - __uint_as_float(ah[q]));
        }

        #pragma unroll
        for (int nt = 0; nt < 8; nt++) {
            int c = wn + nt * 8 + g;
            unsigned bh0 = __float_as_uint(Whs[t][c]);
            unsigned bh1 = __float_as_uint(Whs[t + 4][c]);
            unsigned bl0 = __float_as_uint(Wls[t][c]);
            unsigned bl1 = __float_as_uint(Wls[t + 4][c]);
            mma_tf32(acc[nt], ah, bh0, bh1);
            mma_tf32(acc[nt], ah, bl0, bl1);
            if (!F16A) mma_tf32(acc[nt], al, bh0, bh1);
        }
    }

    int r0 = row_base + wm + g;
    int r1 = r0 + 8;
    float d0 = (r0 < NN) ? dinv[r0] : 0.0f;
    float d1 = (r1 < NN) ? dinv[r1] : 0.0f;
    #pragma unroll
    for (int nt = 0; nt < 8; nt++) {
        int c = wn + nt * 8 + t * 2;
        if (r0 < NN) {
            __half2 h = __float22half2_rn(
                make_float2(acc[nt][0] * d0, acc[nt][1] * d0));
            *reinterpret_cast<__half2*>(&g_out[(long)r0 * D + c]) = h;
        }
        if (r1 < NN) {
            __half2 h = __float22half2_rn(
                make_float2(acc[nt][2] * d1, acc[nt][3] * d1));
            *reinterpret_cast<__half2*>(&g_out[(long)r1 * D + c]) = h;
        }
    }
}

__global__ __launch_bounds__(256) void gemm_tf32_f32_kernel(
    const float* __restrict__ A,
    const float* __restrict__ whi, const float* __restrict__ wlo,
    const float* __restrict__ dinv, __half* __restrict__ g_out)
{
    __shared__ float As[64][132];
    __shared__ float Whs[8][WPAD];
    __shared__ float Wls[8][WPAD];
    gemm_tf32_tile<false>(As, Whs, Wls, A, whi, wlo, dinv, g_out,
                          blockIdx.x * 64, threadIdx.x);
}

__global__ __launch_bounds__(256) void gemm_tf32_f16_kernel(
    const __half* __restrict__ A,
    const float* __restrict__ whi, const float* __restrict__ wlo,
    const float* __restrict__ dinv, __half* __restrict__ g_out)
{
    __shared__ float As[64][132];
    __shared__ float Whs[8][WPAD];
    __shared__ float Wls[8][WPAD];
    gemm_tf32_tile<true>(As, Whs, Wls, A, whi, wlo, dinv, g_out,
                         blockIdx.x * 64, threadIdx.x);
}

// ---------------------------------------------------------------------------
// Gather + finalize over fp16 messages: one warp per node, 4-way unrolled
// (no prefetch — measured regression in round 15).
__device__ __forceinline__ void acc_half4(float4& a, uint2 raw) {
    __half2 h0 = *reinterpret_cast<__half2*>(&raw.x);
    __half2 h1 = *reinterpret_cast<__half2*>(&raw.y);
    float2 f0 = __half22float2(h0);
    float2 f1 = __half22float2(h1);
    a.x += f0.x; a.y += f0.y; a.z += f1.x; a.w += f1.y;
}

__global__ __launch_bounds__(256) void gather_finalize_kernel(
    const uint2* __restrict__ g, const int* __restrict__ row_ptr,
    const int* __restrict__ col, const float* __restrict__ dinv,
    const float4* __restrict__ b,
    uint2* __restrict__ out_h, float4* __restrict__ out_f, int relu_mode)
{
    int warp = (blockIdx.x * blockDim.x + threadIdx.x) >> 5;
    int lane = threadIdx.x & 31;
    if (warp >= NN) return;

    long base = (long)warp * 32 + lane;
    float4 a0 = make_float4(0.f, 0.f, 0.f, 0.f);
    float4 a1 = make_float4(0.f, 0.f, 0.f, 0.f);
    float4 a2 = make_float4(0.f, 0.f, 0.f, 0.f);
    float4 a3 = make_float4(0.f, 0.f, 0.f, 0.f);
    acc_half4(a0, g[base]);                     // self-loop term

    int jb = __ldg(&row_ptr[warp]);
    int je = __ldg(&row_ptr[warp + 1]);
    int j = jb;
    for (; j + 3 < je; j += 4) {
        int s0 = __ldg(&col[j]);
        int s1 = __ldg(&col[j + 1]);
        int s2 = __ldg(&col[j + 2]);
        int s3 = __ldg(&col[j + 3]);
        uint2 v0 = g[(long)s0 * 32 + lane];
        uint2 v1 = g[(long)s1 * 32 + lane];
        uint2 v2 = g[(long)s2 * 32 + lane];
        uint2 v3 = g[(long)s3 * 32 + lane];
        acc_half4(a0, v0); acc_half4(a1, v1);
        acc_half4(a2, v2); acc_half4(a3, v3);
    }
    for (; j < je; j++) {
        int s = __ldg(&col[j]);
        acc_half4(a0, g[(long)s * 32 + lane]);
    }
    a0.x += a1.x + a2.x + a3.x;
    a0.y += a1.y + a2.y + a3.y;
    a0.z += a1.z + a2.z + a3.z;
    a0.w += a1.w + a2.w + a3.w;

    float dv = dinv[warp];
    float4 bb = b[lane];
    float o[4] = { fmaf(a0.x, dv, bb.x), fmaf(a0.y, dv, bb.y),
                   fmaf(a0.z, dv, bb.z), fmaf(a0.w, dv, bb.w) };
    if (relu_mode) {
        #pragma unroll
        for (int k = 0; k < 4; k++) o[k] = fmaxf(o[k], 0.0f);
    } else {
        #pragma unroll
        for (int k = 0; k < 4; k++) o[k] = (o[k] > 0.0f) ? o[k] : expm1f(o[k]);
    }
    if (out_h) {
        __half2 h0 = __floats2half2_rn(o[0], o[1]);
        __half2 h1 = __floats2half2_rn(o[2], o[3]);
        uint2 packed;
        packed.x = *reinterpret_cast<unsigned*>(&h0);
        packed.y = *reinterpret_cast<unsigned*>(&h1);
        out_h[base] = packed;
    } else {
        out_f[base] = make_float4(o[0], o[1], o[2], o[3]);
    }
}

// ---------------------------------------------------------------------------
extern "C" void kernel_launch(void* const* d_in, const int* in_sizes, int n_in,
                              void* d_out, int out_size)
{
    const float* x  = (const float*)d_in[0];
    const float* W1 = (const float*)d_in[1]; const float* b1 = (const float*)d_in[2];
    const float* W2 = (const float*)d_in[3]; const float* b2 = (const float*)d_in[4];
    const float* W3 = (const float*)d_in[5]; const float* b3 = (const float*)d_in[6];
    const float* W4 = (const float*)d_in[7]; const float* b4 = (const float*)d_in[8];
    const int* ei1 = (const int*)d_in[9];
    const int* ei2 = (const int*)d_in[10];
    const int E1 = in_sizes[9] / 2;
    const int E2 = in_sizes[10] / 2;

    __half *ga, *gb, *acth;
    float *dinv1, *dinv2, *whi, *wlo;
    int *cnt1, *cnt2, *rp1, *rp2, *cur1, *cur2, *col1, *col2, *p1, *p2;
    cudaGetSymbolAddress((void**)&ga,   g_ga);
    cudaGetSymbolAddress((void**)&gb,   g_gb);
    cudaGetSymbolAddress((void**)&acth, g_acth);
    cudaGetSymbolAddress((void**)&dinv1, g_dinv1);
    cudaGetSymbolAddress((void**)&dinv2, g_dinv2);
    cudaGetSymbolAddress((void**)&cnt1, g_cnt1);
    cudaGetSymbolAddress((void**)&cnt2, g_cnt2);
    cudaGetSymbolAddress((void**)&rp1,  g_rowptr1);
    cudaGetSymbolAddress((void**)&rp2,  g_rowptr2);
    cudaGetSymbolAddress((void**)&cur1, g_cursor1);
    cudaGetSymbolAddress((void**)&cur2, g_cursor2);
    cudaGetSymbolAddress((void**)&col1, g_col1);
    cudaGetSymbolAddress((void**)&col2, g_col2);
    cudaGetSymbolAddress((void**)&p1,   g_part1);
    cudaGetSymbolAddress((void**)&p2,   g_part2);
    cudaGetSymbolAddress((void**)&whi,  g_whi);
    cudaGetSymbolAddress((void**)&wlo,  g_wlo);

    float* out_z = (float*)d_out;
    float* out_x = (float*)d_out + (long)NN * D;

    const int gat_blocks  = (NN * 32 + 255) / 256;
    const int nedge2 = (E1 >> 1) + (E2 >> 1) + 2;
    const int edge_blocks = (nedge2 + 255) / 256;

    // ---- CSR build ----
    splitw_count_kernel<<<SPLITW_BLOCKS + edge_blocks, 256>>>(
        W1, W2, W3, W4, whi, wlo, ei1, E1, ei2, E2, cnt1, cnt2, rp1, rp2);
    partial_dinv_kernel<<<2 * NPART, 256>>>(cnt1, dinv1, p1, cnt2, dinv2, p2);
    scan_tiles_kernel<<<2 * NPART, 1024>>>(cnt1, rp1, cur1, p1, cnt2, rp2, cur2, p2);
    fill_both_kernel<<<edge_blocks, 256>>>(ei1, E1, cur1, col1, ei2, E2, cur2, col2);

    // gemm1 (fp32 A, 3-pass): ga = (x @ W1) * dinv1
    gemm_tf32_f32_kernel<<<GEMM_BLOCKS, 256>>>(x, whi + 0 * D * D, wlo + 0 * D * D,
                                               dinv1, ga);
    // gather1 (elu) -> acth (fp16)
    gather_finalize_kernel<<<gat_blocks, 256>>>(
        (const uint2*)ga, rp1, col1, dinv1, (const float4*)b1,
        (uint2*)acth, nullptr, 0);
    // gemm2 (fp16 A, 2-pass): acth -> gb (*dinv2)
    gemm_tf32_f16_kernel<<<GEMM_BLOCKS, 256>>>(acth, whi + 1 * D * D, wlo + 1 * D * D,
                                               dinv2, gb);
    // gather2 (elu) -> out_z (fp32; layer-3 GEMM reads it directly)
    gather_finalize_kernel<<<gat_blocks, 256>>>(
        (const uint2*)gb, rp2, col2, dinv2, (const float4*)b2,
        nullptr, (float4*)out_z, 0);
    // gemm3 (fp32 A, 3-pass): out_z -> ga (*dinv1)
    gemm_tf32_f32_kernel<<<GEMM_BLOCKS, 256>>>(out_z, whi + 2 * D * D, wlo + 2 * D * D,
                                               dinv1, ga);
    // gather3 (elu) -> acth (fp16)
    gather_finalize_kernel<<<gat_blocks, 256>>>(
        (const uint2*)ga, rp1, col1, dinv1, (const float4*)b3,
        (uint2*)acth, nullptr, 0);
    // gemm4 (fp16 A, 2-pass): acth -> gb (*dinv2)
    gemm_tf32_f16_kernel<<<GEMM_BLOCKS, 256>>>(acth, whi + 3 * D * D, wlo + 3 * D * D,
                                               dinv2, gb);
    // gather4 (relu) -> out_x (fp32)
    gather_finalize_kernel<<<gat_blocks, 256>>>(
        (const uint2*)gb, rp2, col2, dinv2, (const float4*)b4,
        nullptr, (float4*)out_x, 1);
}

// round 17
// speedup vs baseline: 1.0668x; 1.0229x over previous
#include <cuda_runtime.h>
#include <cuda_fp16.h>
#include <math.h>

#define NN 50000
#define D 128
#define EMAX 800000
#define TILE 1024
#define NPART ((NN + TILE - 1) / TILE)   // 49
#define GEMM_BLOCKS ((NN + 63) / 64)     // 782
#define WPAD 136
#define SPLITW_BLOCKS (4 * D * D / 256)  // 256

// ---- device scratch (no allocations allowed; zero-initialized at load) ----
__device__ __half g_ga[(size_t)NN * D];   // fp16 message buffers (pre-activation)
__device__ __half g_gb[(size_t)NN * D];
__device__ __half g_acth[(size_t)NN * D]; // fp16 activation buffer (layers 1,3)
__device__ float g_dinv1[NN];
__device__ float g_dinv2[NN];
__device__ int   g_cnt1[NN];              // kept zeroed by scan_tiles_kernel
__device__ int   g_cnt2[NN];
__device__ int   g_rowptr1[NN + 1];
__device__ int   g_rowptr2[NN + 1];
__device__ int   g_cursor1[NN];
__device__ int   g_cursor2[NN];
__device__ int   g_col1[EMAX];
__device__ int   g_col2[EMAX];
__device__ int   g_part1[NPART];
__device__ int   g_part2[NPART];
__device__ float g_whi[4 * D * D];        // tf32-rounded hi parts of W1..W4
__device__ float g_wlo[4 * D * D];        // tf32-rounded lo parts

// ---- tf32 helpers ----
__device__ __forceinline__ unsigned f2tf32(float f) {
    unsigned r;
    asm("cvt.rna.tf32.f32 %0, %1;" : "=r"(r) : "f"(f));
    return r;
}
__device__ __forceinline__ void mma_tf32(float* c, const unsigned* a,
                                         unsigned b0, unsigned b1) {
    asm volatile(
        "mma.sync.aligned.m16n8k8.row.col.f32.tf32.tf32.f32 "
        "{%0,%1,%2,%3}, {%4,%5,%6,%7}, {%8,%9}, {%0,%1,%2,%3};"
        : "+f"(c[0]), "+f"(c[1]), "+f"(c[2]), "+f"(c[3])
        : "r"(a[0]), "r"(a[1]), "r"(a[2]), "r"(a[3]), "r"(b0), "r"(b1));
}

// ---------------------------------------------------------------------------
// W tf32-split only (runs on side stream, feeds gemm1 + later gemms).
__global__ void splitw_kernel(
    const float* __restrict__ W1, const float* __restrict__ W2,
    const float* __restrict__ W3, const float* __restrict__ W4,
    float* __restrict__ whi, float* __restrict__ wlo,
    int* __restrict__ rp1, int* __restrict__ rp2, int E1, int E2)
{
    int i = blockIdx.x * blockDim.x + threadIdx.x;
    int l = i >> 14;
    int j = i & 16383;
    const float* W = (l == 0) ? W1 : (l == 1) ? W2 : (l == 2) ? W3 : W4;
    float f = W[j];
    float hf = __uint_as_float(f2tf32(f));
    whi[i] = hf;
    wlo[i] = __uint_as_float(f2tf32(f - hf));
    if (i == 0) { rp1[NN] = E1; rp2[NN] = E2; }
}

// Degree count, 2 edges/thread (measured-best grid size).
__global__ void count_kernel(
    const int* __restrict__ ei1, int E1,
    const int* __restrict__ ei2, int E2,
    int* __restrict__ c1, int* __restrict__ c2)
{
    int h1 = E1 >> 1, h2 = E2 >> 1;
    int i = blockIdx.x * blockDim.x + threadIdx.x;
    if (i < h1) {
        int2 d = reinterpret_cast<const int2*>(ei1 + E1)[i];
        atomicAdd(&c1[d.x], 1);
        atomicAdd(&c1[d.y], 1);
    } else if (i < h1 + h2) {
        int2 d = reinterpret_cast<const int2*>(ei2 + E2)[i - h1];
        atomicAdd(&c2[d.x], 1);
        atomicAdd(&c2[d.y], 1);
    } else {
        int k = i - h1 - h2;
        if (k == 0 && (E1 & 1)) atomicAdd(&c1[ei1[E1 + E1 - 1]], 1);
        if (k == 1 && (E2 & 1)) atomicAdd(&c2[ei2[E2 + E2 - 1]], 1);
    }
}

__global__ __launch_bounds__(256) void partial_dinv_kernel(
    const int* __restrict__ c1, float* __restrict__ d1, int* __restrict__ p1,
    const int* __restrict__ c2, float* __restrict__ d2, int* __restrict__ p2)
{
    int set = (blockIdx.x >= NPART) ? 1 : 0;
    int b = blockIdx.x - set * NPART;
    const int* c = set ? c2 : c1;
    float* dv    = set ? d2 : d1;
    int* part    = set ? p2 : p1;

    __shared__ int wsum[8];
    int tid = threadIdx.x;
    int base = b * TILE + tid * 4;
    int s = 0;
    #pragma unroll
    for (int k = 0; k < 4; k++) {
        int i = base + k;
        if (i < NN) {
            int v = c[i];
            s += v;
            dv[i] = rsqrtf((float)v + 1.0f);
        }
    }
    #pragma unroll
    for (int off = 16; off > 0; off >>= 1)
        s += __shfl_down_sync(0xFFFFFFFFu, s, off);
    if ((tid & 31) == 0) wsum[tid >> 5] = s;
    __syncthreads();
    if (tid < 8) {
        int t = wsum[tid];
        #pragma unroll
        for (int off = 4; off > 0; off >>= 1)
            t += __shfl_down_sync(0xFFu, t, off);
        if (tid == 0) part[b] = t;
    }
}

// Per-tile scan; block offset computed in-block from raw tile sums (part[]).
// Also zeroes cnt (maintains counts-are-zero invariant for graph replay).
__global__ __launch_bounds__(1024) void scan_tiles_kernel(
    int* __restrict__ c1, int* __restrict__ rp1, int* __restrict__ cur1,
    const int* __restrict__ p1,
    int* __restrict__ c2, int* __restrict__ rp2, int* __restrict__ cur2,
    const int* __restrict__ p2)
{
    int set = (blockIdx.x >= NPART) ? 1 : 0;
    int b = blockIdx.x - set * NPART;
    int* cnt        = set ? c2 : c1;
    int* rp         = set ? rp2 : rp1;
    int* cur        = set ? cur2 : cur1;
    const int* part = set ? p2 : p1;

    __shared__ int warp_sums[32];
    __shared__ int s_off;
    int tid = threadIdx.x;
    int lane = tid & 31;
    int wid = tid >> 5;

    if (tid == 0) s_off = 0;
    __syncthreads();
    if (tid < b) atomicAdd(&s_off, part[tid]);   // b <= 48 raw tile sums

    int i = b * TILE + tid;
    int v = (i < NN) ? cnt[i] : 0;
    int incl = v;
    #pragma unroll
    for (int off = 1; off < 32; off <<= 1) {
        int t = __shfl_up_sync(0xFFFFFFFFu, incl, off);
        if (lane >= off) incl += t;
    }
    if (lane == 31) warp_sums[wid] = incl;
    __syncthreads();
    if (wid == 0) {
        int s = warp_sums[lane];
        #pragma unroll
        for (int off = 1; off < 32; off <<= 1) {
            int t = __shfl_up_sync(0xFFFFFFFFu, s, off);
            if (lane >= off) s += t;
        }
        warp_sums[lane] = s;
    }
    __syncthreads();
    int woff = (wid > 0) ? warp_sums[wid - 1] : 0;
    int excl = incl - v + woff + s_off;
    if (i < NN) { rp[i] = excl; cur[i] = excl; cnt[i] = 0; }
}

// CSR fill: 2 edges/thread — measured-best grid/MLP balance.
__global__ void fill_both_kernel(const int* __restrict__ ei1, int E1,
                                 int* __restrict__ cur1, int* __restrict__ col1,
                                 const int* __restrict__ ei2, int E2,
                                 int* __restrict__ cur2, int* __restrict__ col2)
{
    int h1 = E1 >> 1, h2 = E2 >> 1;
    int i = blockIdx.x * blockDim.x + threadIdx.x;
    if (i < h1) {
        int2 s = reinterpret_cast<const int2*>(ei1)[i];
        int2 d = reinterpret_cast<const int2*>(ei1 + E1)[i];
        col1[atomicAdd(&cur1[d.x], 1)] = s.x;
        col1[atomicAdd(&cur1[d.y], 1)] = s.y;
    } else if (i < h1 + h2) {
        int2 s = reinterpret_cast<const int2*>(ei2)[i - h1];
        int2 d = reinterpret_cast<const int2*>(ei2 + E2)[i - h1];
        col2[atomicAdd(&cur2[d.x], 1)] = s.x;
        col2[atomicAdd(&cur2[d.y], 1)] = s.y;
    } else {
        int k = i - h1 - h2;
        if (k == 0 && (E1 & 1))
            col1[atomicAdd(&cur1[ei1[E1 + E1 - 1]], 1)] = ei1[E1 - 1];
        if (k == 1 && (E2 & 1))
            col2[atomicAdd(&cur2[ei2[E2 + E2 - 1]], 1)] = ei2[E2 - 1];
    }
}

// ---------------------------------------------------------------------------
// tf32 GEMM tile. F16A=false: fp32 A, 3-pass. F16A=true: fp16 A, 2-pass.
// dinv == nullptr -> no row scaling (used by gemm1; scale applied per-edge
// in gather1 instead, removing gemm1's dependency on the CSR chain).
template <bool F16A>
__device__ __forceinline__ void gemm_tf32_tile(
    float (*As)[132], float (*Whs)[WPAD], float (*Wls)[WPAD],
    const void* __restrict__ Aptr,
    const float* __restrict__ whi, const float* __restrict__ wlo,
    const float* __restrict__ dinv, __half* __restrict__ g_out,
    int row_base, int tid)
{
    if (F16A) {
        const uint4* Ah = reinterpret_cast<const uint4*>(Aptr);
        #pragma unroll
        for (int i = tid; i < 64 * 16; i += 256) {
            int r = i >> 4, u = i & 15;
            uint4 raw = make_uint4(0u, 0u, 0u, 0u);
            if (row_base + r < NN)
                raw = Ah[(long)(row_base + r) * 16 + u];
            const __half2* hp = reinterpret_cast<const __half2*>(&raw);
            float* dst = &As[r][u * 8];
            #pragma unroll
            for (int p = 0; p < 4; p++) {
                float2 f = __half22float2(hp[p]);
                dst[p * 2]     = f.x;
                dst[p * 2 + 1] = f.y;
            }
        }
    } else {
        const float4* Af = reinterpret_cast<const float4*>(Aptr);
        #pragma unroll
        for (int i = tid; i < 64 * 32; i += 256) {
            int r = i >> 5, c4 = i & 31;
            float4 v = make_float4(0.f, 0.f, 0.f, 0.f);
            if (row_base + r < NN)
                v = Af[(long)(row_base + r) * 32 + c4];
            *reinterpret_cast<float4*>(&As[r][c4 * 4]) = v;
        }
    }

    const int lane = tid & 31;
    const int wid = tid >> 5;
    const int wm = (wid & 3) * 16;
    const int wn = (wid >> 2) * 64;
    const int g = lane >> 2;
    const int t = lane & 3;

    float acc[8][4];
    #pragma unroll
    for (int nt = 0; nt < 8; nt++)
        #pragma unroll
        for (int c = 0; c < 4; c++) acc[nt][c] = 0.0f;

    for (int kc = 0; kc < D; kc += 8) {
        __syncthreads();
        #pragma unroll
        for (int i = tid; i < 512; i += 256) {
            int m = i >> 8;
            int j = i & 255;
            int r = j >> 5, c4 = j & 31;
            const float4* src = reinterpret_cast<const float4*>(m ? wlo : whi);
            float4 v = src[(kc + r) * 32 + c4];
            float (*dst)[WPAD] = m ? Wls : Whs;
            *reinterpret_cast<float4*>(&dst[r][c4 * 4]) = v;
        }
        __syncthreads();

        float af[4] = { As[wm + g][kc + t],     As[wm + g + 8][kc + t],
                        As[wm + g][kc + t + 4], As[wm + g + 8][kc + t + 4] };
        unsigned ah[4], al[4];
        #pragma unroll
        for (int q = 0; q < 4; q++) {
            ah[q] = f2tf32(af[q]);
            if (!F16A)
                al[q] = f2tf32(af[q] - __uint_as_float(ah[q]));
        }

        #pragma unroll
        for (int nt = 0; nt < 8; nt++) {
            int c = wn + nt * 8 + g;
            unsigned bh0 = __float_as_uint(Whs[t][c]);
            unsigned bh1 = __float_as_uint(Whs[t + 4][c]);
            unsigned bl0 = __float_as_uint(Wls[t][c]);
            unsigned bl1 = __float_as_uint(Wls[t + 4][c]);
            mma_tf32(acc[nt], ah, bh0, bh1);
            mma_tf32(acc[nt], ah, bl0, bl1);
            if (!F16A) mma_tf32(acc[nt], al, bh0, bh1);
        }
    }

    int r0 = row_base + wm + g;
    int r1 = r0 + 8;
    float d0 = 1.0f, d1 = 1.0f;
    if (dinv) {
        d0 = (r0 < NN) ? dinv[r0] : 0.0f;
        d1 = (r1 < NN) ? dinv[r1] : 0.0f;
    }
    #pragma unroll
    for (int nt = 0; nt < 8; nt++) {
        int c = wn + nt * 8 + t * 2;
        if (r0 < NN) {
            __half2 h = __float22half2_rn(
                make_float2(acc[nt][0] * d0, acc[nt][1] * d0));
            *reinterpret_cast<__half2*>(&g_out[(long)r0 * D + c]) = h;
        }
        if (r1 < NN) {
            __half2 h = __float22half2_rn(
                make_float2(acc[nt][2] * d1, acc[nt][3] * d1));
            *reinterpret_cast<__half2*>(&g_out[(long)r1 * D + c]) = h;
        }
    }
}

__global__ __launch_bounds__(256) void gemm_tf32_f32_kernel(
    const float* __restrict__ A,
    const float* __restrict__ whi, const float* __restrict__ wlo,
    const float* __restrict__ dinv, __half* __restrict__ g_out)
{
    __shared__ float As[64][132];
    __shared__ float Whs[8][WPAD];
    __shared__ float Wls[8][WPAD];
    gemm_tf32_tile<false>(As, Whs, Wls, A, whi, wlo, dinv, g_out,
                          blockIdx.x * 64, threadIdx.x);
}

__global__ __launch_bounds__(256) void gemm_tf32_f16_kernel(
    const __half* __restrict__ A,
    const float* __restrict__ whi, const float* __restrict__ wlo,
    const float* __restrict__ dinv, __half* __restrict__ g_out)
{
    __shared__ float As[64][132];
    __shared__ float Whs[8][WPAD];
    __shared__ float Wls[8][WPAD];
    gemm_tf32_tile<true>(As, Whs, Wls, A, whi, wlo, dinv, g_out,
                         blockIdx.x * 64, threadIdx.x);
}

// ---------------------------------------------------------------------------
// Gather + finalize over fp16 messages: one warp per node, 4-way unrolled.
// dinv_src == nullptr: messages pre-scaled (folded). Otherwise per-edge
// scaling: out = act(dv*(dv*g_self + sum dinv[s]*g_s) + b).
__device__ __forceinline__ void acc_half4(float4& a, uint2 raw) {
    __half2 h0 = *reinterpret_cast<__half2*>(&raw.x);
    __half2 h1 = *reinterpret_cast<__half2*>(&raw.y);
    float2 f0 = __half22float2(h0);
    float2 f1 = __half22float2(h1);
    a.x += f0.x; a.y += f0.y; a.z += f1.x; a.w += f1.y;
}
__device__ __forceinline__ void acc_half4s(float4& a, uint2 raw, float sc) {
    __half2 h0 = *reinterpret_cast<__half2*>(&raw.x);
    __half2 h1 = *reinterpret_cast<__half2*>(&raw.y);
    float2 f0 = __half22float2(h0);
    float2 f1 = __half22float2(h1);
    a.x = fmaf(sc, f0.x, a.x); a.y = fmaf(sc, f0.y, a.y);
    a.z = fmaf(sc, f1.x, a.z); a.w = fmaf(sc, f1.y, a.w);
}

template <bool ESCALE>
__device__ __forceinline__ void gather_body(
    const uint2* __restrict__ g, const int* __restrict__ row_ptr,
    const int* __restrict__ col, const float* __restrict__ dinv,
    const float4* __restrict__ b,
    uint2* __restrict__ out_h, float4* __restrict__ out_f, int relu_mode)
{
    int warp = (blockIdx.x * blockDim.x + threadIdx.x) >> 5;
    int lane = threadIdx.x & 31;
    if (warp >= NN) return;

    long base = (long)warp * 32 + lane;
    float dv = dinv[warp];
    float4 a0 = make_float4(0.f, 0.f, 0.f, 0.f);
    float4 a1 = make_float4(0.f, 0.f, 0.f, 0.f);
    float4 a2 = make_float4(0.f, 0.f, 0.f, 0.f);
    float4 a3 = make_float4(0.f, 0.f, 0.f, 0.f);
    if (ESCALE) acc_half4s(a0, g[base], dv);
    else        acc_half4(a0, g[base]);

    int jb = __ldg(&row_ptr[warp]);
    int je = __ldg(&row_ptr[warp + 1]);
    int j = jb;
    for (; j + 3 < je; j += 4) {
        int s0 = __ldg(&col[j]);
        int s1 = __ldg(&col[j + 1]);
        int s2 = __ldg(&col[j + 2]);
        int s3 = __ldg(&col[j + 3]);
        uint2 v0 = g[(long)s0 * 32 + lane];
        uint2 v1 = g[(long)s1 * 32 + lane];
        uint2 v2 = g[(long)s2 * 32 + lane];
        uint2 v3 = g[(long)s3 * 32 + lane];
        if (ESCALE) {
            acc_half4s(a0, v0, __ldg(&dinv[s0]));
            acc_half4s(a1, v1, __ldg(&dinv[s1]));
            acc_half4s(a2, v2, __ldg(&dinv[s2]));
            acc_half4s(a3, v3, __ldg(&dinv[s3]));
        } else {
            acc_half4(a0, v0); acc_half4(a1, v1);
            acc_half4(a2, v2); acc_half4(a3, v3);
        }
    }
    for (; j < je; j++) {
        int s = __ldg(&col[j]);
        if (ESCALE) acc_half4s(a0, g[(long)s * 32 + lane], __ldg(&dinv[s]));
        else        acc_half4(a0, g[(long)s * 32 + lane]);
    }
    a0.x += a1.x + a2.x + a3.x;
    a0.y += a1.y + a2.y + a3.y;
    a0.z += a1.z + a2.z + a3.z;
    a0.w += a1.w + a2.w + a3.w;

    float4 bb = b[lane];
    float o[4] = { fmaf(a0.x, dv, bb.x), fmaf(a0.y, dv, bb.y),
                   fmaf(a0.z, dv, bb.z), fmaf(a0.w, dv, bb.w) };
    if (relu_mode) {
        #pragma unroll
        for (int k = 0; k < 4; k++) o[k] = fmaxf(o[k], 0.0f);
    } else {
        #pragma unroll
        for (int k = 0; k < 4; k++) o[k] = (o[k] > 0.0f) ? o[k] : expm1f(o[k]);
    }
    if (out_h) {
        __half2 h0 = __floats2half2_rn(o[0], o[1]);
        __half2 h1 = __floats2half2_rn(o[2], o[3]);
        uint2 packed;
        packed.x = *reinterpret_cast<unsigned*>(&h0);
        packed.y = *reinterpret_cast<unsigned*>(&h1);
        out_h[base] = packed;
    } else {
        out_f[base] = make_float4(o[0], o[1], o[2], o[3]);
    }
}

__global__ __launch_bounds__(256) void gather_finalize_kernel(
    const uint2* __restrict__ g, const int* __restrict__ row_ptr,
    const int* __restrict__ col, const float* __restrict__ dinv,
    const float4* __restrict__ b,
    uint2* __restrict__ out_h, float4* __restrict__ out_f, int relu_mode)
{
    gather_body<false>(g, row_ptr, col, dinv, b, out_h, out_f, relu_mode);
}

__global__ __launch_bounds__(256) void gather_finalize_escale_kernel(
    const uint2* __restrict__ g, const int* __restrict__ row_ptr,
    const int* __restrict__ col, const float* __restrict__ dinv,
    const float4* __restrict__ b,
    uint2* __restrict__ out_h, float4* __restrict__ out_f, int relu_mode)
{
    gather_body<true>(g, row_ptr, col, dinv, b, out_h, out_f, relu_mode);
}

// ---------------------------------------------------------------------------
extern "C" void kernel_launch(void* const* d_in, const int* in_sizes, int n_in,
                              void* d_out, int out_size)
{
    const float* x  = (const float*)d_in[0];
    const float* W1 = (const float*)d_in[1]; const float* b1 = (const float*)d_in[2];
    const float* W2 = (const float*)d_in[3]; const float* b2 = (const float*)d_in[4];
    const float* W3 = (const float*)d_in[5]; const float* b3 = (const float*)d_in[6];
    const float* W4 = (const float*)d_in[7]; const float* b4 = (const float*)d_in[8];
    const int* ei1 = (const int*)d_in[9];
    const int* ei2 = (const int*)d_in[10];
    const int E1 = in_sizes[9] / 2;
    const int E2 = in_sizes[10] / 2;

    __half *ga, *gb, *acth;
    float *dinv1, *dinv2, *whi, *wlo;
    int *cnt1, *cnt2, *rp1, *rp2, *cur1, *cur2, *col1, *col2, *p1, *p2;
    cudaGetSymbolAddress((void**)&ga,   g_ga);
    cudaGetSymbolAddress((void**)&gb,   g_gb);
    cudaGetSymbolAddress((void**)&acth, g_acth);
    cudaGetSymbolAddress((void**)&dinv1, g_dinv1);
    cudaGetSymbolAddress((void**)&dinv2, g_dinv2);
    cudaGetSymbolAddress((void**)&cnt1, g_cnt1);
    cudaGetSymbolAddress((void**)&cnt2, g_cnt2);
    cudaGetSymbolAddress((void**)&rp1,  g_rowptr1);
    cudaGetSymbolAddress((void**)&rp2,  g_rowptr2);
    cudaGetSymbolAddress((void**)&cur1, g_cursor1);
    cudaGetSymbolAddress((void**)&cur2, g_cursor2);
    cudaGetSymbolAddress((void**)&col1, g_col1);
    cudaGetSymbolAddress((void**)&col2, g_col2);
    cudaGetSymbolAddress((void**)&p1,   g_part1);
    cudaGetSymbolAddress((void**)&p2,   g_part2);
    cudaGetSymbolAddress((void**)&whi,  g_whi);
    cudaGetSymbolAddress((void**)&wlo,  g_wlo);

    // One-time side stream + fork/join events (created on the uncaptured
    // correctness call; same-precedent as prior cudaFuncSetAttribute static).
    static cudaStream_t s2 = nullptr;
    static cudaEvent_t ev_fork = nullptr, ev_join = nullptr;
    if (!s2) {
        cudaStreamCreateWithFlags(&s2, cudaStreamNonBlocking);
        cudaEventCreateWithFlags(&ev_fork, cudaEventDisableTiming);
        cudaEventCreateWithFlags(&ev_join, cudaEventDisableTiming);
    }

    float* out_z = (float*)d_out;
    float* out_x = (float*)d_out + (long)NN * D;

    const int gat_blocks  = (NN * 32 + 255) / 256;
    const int nedge2 = (E1 >> 1) + (E2 >> 1) + 2;
    const int edge_blocks = (nedge2 + 255) / 256;

    // ---- Fork: side stream runs W-split + unscaled gemm1 concurrently
    //      with the CSR build chain on the capture (legacy) stream. ----
    cudaEventRecord(ev_fork, 0);
    cudaStreamWaitEvent(s2, ev_fork, 0);

    splitw_kernel<<<SPLITW_BLOCKS, 256, 0, s2>>>(W1, W2, W3, W4, whi, wlo,
                                                 rp1, rp2, E1, E2);
    gemm_tf32_f32_kernel<<<GEMM_BLOCKS, 256, 0, s2>>>(
        x, whi + 0 * D * D, wlo + 0 * D * D, nullptr, ga);  // unscaled
    cudaEventRecord(ev_join, s2);

    // CSR build on the main stream (independent of the side chain)
    count_kernel<<<edge_blocks, 256>>>(ei1, E1, ei2, E2, cnt1, cnt2);
    partial_dinv_kernel<<<2 * NPART, 256>>>(cnt1, dinv1, p1, cnt2, dinv2, p2);
    scan_tiles_kernel<<<2 * NPART, 1024>>>(cnt1, rp1, cur1, p1, cnt2, rp2, cur2, p2);
    fill_both_kernel<<<edge_blocks, 256>>>(ei1, E1, cur1, col1, ei2, E2, cur2, col2);

    cudaStreamWaitEvent(0, ev_join, 0);   // join before gather1

    // gather1 (elu, per-edge dinv scaling) -> acth (fp16)
    gather_finalize_escale_kernel<<<gat_blocks, 256>>>(
        (const uint2*)ga, rp1, col1, dinv1, (const float4*)b1,
        (uint2*)acth, nullptr, 0);
    // gemm2 (fp16 A, 2-pass): acth -> gb (*dinv2)
    gemm_tf32_f16_kernel<<<GEMM_BLOCKS, 256>>>(acth, whi + 1 * D * D, wlo + 1 * D * D,
                                               dinv2, gb);
    // gather2 (elu) -> out_z (fp32; layer-3 GEMM reads it directly)
    gather_finalize_kernel<<<gat_blocks, 256>>>(
        (const uint2*)gb, rp2, col2, dinv2, (const float4*)b2,
        nullptr, (float4*)out_z, 0);
    // gemm3 (fp32 A, 3-pass): out_z -> ga (*dinv1)
    gemm_tf32_f32_kernel<<<GEMM_BLOCKS, 256>>>(out_z, whi + 2 * D * D, wlo + 2 * D * D,
                                               dinv1, ga);
    // gather3 (elu) -> acth (fp16)
    gather_finalize_kernel<<<gat_blocks, 256>>>(
        (const uint2*)ga, rp1, col1, dinv1, (const float4*)b3,
        (uint2*)acth, nullptr, 0);
    // gemm4 (fp16 A, 2-pass): acth -> gb (*dinv2)
    gemm_tf32_f16_kernel<<<GEMM_BLOCKS, 256>>>(acth, whi + 3 * D * D, wlo + 3 * D * D,
                                               dinv2, gb);
    // gather4 (relu) -> out_x (fp32)
    gather_finalize_kernel<<<gat_blocks, 256>>>(
        (const uint2*)gb, rp2, col2, dinv2, (const float4*)b4,
        nullptr, (float4*)out_x, 1);
}